// round 3
// baseline (speedup 1.0000x reference)
#include <cuda_runtime.h>
#include <cstdint>

#define MAXN 100000
#define MAXE 1000000
#define DIN 128
#define DH  64

// ---- scratch (no allocations allowed; referenced only from device code) ----
__device__ int   g_deg[MAXN];
__device__ int   g_rowptr[MAXN + 1];
__device__ int   g_cursor[MAXN];
__device__ int   g_col[MAXE];
__device__ float g_dinv[MAXN];
__device__ __align__(16) float g_h[(size_t)MAXN * 64];  // dinv-scaled GEMM output
__device__ __align__(16) float g_a[(size_t)MAXN * 64];  // layer-1 activations
__device__ int   g_is64;                                 // edge dtype flag

// ---------------- dtype detection: int64 vs int32 edge_index ----------------
// If buffer is int32, interpreting as int64 merges two random indices; the high
// word is almost surely nonzero -> value >= 2^32 -> out of [0,n).
__global__ void k_detect(const void* ei, int n, int e) {
    const long long* p = (const long long*)ei;
    int m = e < 64 ? e : 64;
    int ok = 1;
    for (int i = 0; i < m; i++) {
        long long v = p[i];
        if (v < 0 || v >= n) { ok = 0; break; }
    }
    g_is64 = ok;
}

// ---------------- init: zero deg + cursor ----------------
__global__ void k_init(int n) {
    int i = blockIdx.x * blockDim.x + threadIdx.x;
    if (i < n) { g_deg[i] = 0; g_cursor[i] = 0; }
}

// ---------------- degree count over dst ----------------
__global__ void k_count(const void* __restrict__ ei, int n, int e) {
    int i = blockIdx.x * blockDim.x + threadIdx.x;
    if (i >= e) return;
    int v;
    if (g_is64) v = (int)((const long long*)ei + e)[i];
    else        v = ((const int*)ei + e)[i];
    if ((unsigned)v < (unsigned)n) atomicAdd(&g_deg[v], 1);
}

// ---------------- single-block exclusive scan + dinv ----------------
// deg EXCLUDES the self loop; dinv uses deg+1 (self-loop included, always > 0).
__global__ void k_scan(int n) {
    __shared__ int warp_tot[32];
    int tid  = threadIdx.x;
    int per  = (n + 1023) / 1024;
    int lo   = tid * per;
    int hi   = lo + per; if (hi > n) hi = n;
    if (lo > n) lo = n;

    int sum = 0;
    for (int i = lo; i < hi; i++) sum += g_deg[i];

    int lane = tid & 31, w = tid >> 5;
    int incl = sum;
    #pragma unroll
    for (int off = 1; off < 32; off <<= 1) {
        int t = __shfl_up_sync(0xffffffffu, incl, off);
        if (lane >= off) incl += t;
    }
    if (lane == 31) warp_tot[w] = incl;
    __syncthreads();
    if (w == 0) {
        int v = warp_tot[lane];
        int iv = v;
        #pragma unroll
        for (int off = 1; off < 32; off <<= 1) {
            int t = __shfl_up_sync(0xffffffffu, iv, off);
            if (lane >= off) iv += t;
        }
        warp_tot[lane] = iv - v;   // exclusive warp offsets
    }
    __syncthreads();

    int excl = warp_tot[w] + (incl - sum);
    int run = excl;
    for (int i = lo; i < hi; i++) {
        int d = g_deg[i];
        g_rowptr[i] = run;
        run += d;
        g_dinv[i] = rsqrtf((float)(d + 1));
    }
    if (tid == 1023) g_rowptr[n] = excl + sum;  // thread 1023's chunk is empty (n=100000)
}

// ---------------- CSR fill (counting-sort placement) ----------------
__global__ void k_fill(const void* __restrict__ ei, int n, int e) {
    int i = blockIdx.x * blockDim.x + threadIdx.x;
    if (i >= e) return;
    int s, v;
    if (g_is64) {
        s = (int)((const long long*)ei)[i];
        v = (int)((const long long*)ei + e)[i];
    } else {
        s = ((const int*)ei)[i];
        v = ((const int*)ei + e)[i];
    }
    if ((unsigned)v < (unsigned)n && (unsigned)s < (unsigned)n) {
        int pos = g_rowptr[v] + atomicAdd(&g_cursor[v], 1);
        g_col[pos] = s;
    }
}

// ---------------- GEMM: g_h[i][j] = dinv[i] * dot(in[i,:], W[:,j]) ----------------
// FROM_GA: read input rows from g_a instead of the pointer argument.
// Block: 256 threads -> 64 rows x 64 cols, 4x4 register tile per thread.
template<int K, bool FROM_GA>
__global__ void k_gemm(const float* __restrict__ in, const float* __restrict__ W, int n) {
    const int BM = 64, BK = 64;
    __shared__ float Xs[BM][BK + 4];
    __shared__ float Ws[BK][64];
    int tid = threadIdx.x;
    int tx = tid & 15, ty = tid >> 4;
    int row0 = blockIdx.x * BM;

    const float* src = FROM_GA ? (const float*)g_a : in;

    float acc[4][4] = {};

    for (int k0 = 0; k0 < K; k0 += BK) {
        for (int l = tid; l < BK * 64 / 4; l += 256) {
            ((float4*)Ws)[l] = ((const float4*)(W + (size_t)k0 * 64))[l];
        }
        for (int l = tid; l < BM * BK / 4; l += 256) {
            int r = l >> 4;
            int c4 = l & 15;
            int grow = row0 + r;
            float4 v = make_float4(0.f, 0.f, 0.f, 0.f);
            if (grow < n)
                v = *(const float4*)(src + (size_t)grow * K + k0 + c4 * 4);
            *(float4*)&Xs[r][c4 * 4] = v;
        }
        __syncthreads();

        #pragma unroll
        for (int k = 0; k < BK; k++) {
            float a[4];
            #pragma unroll
            for (int r = 0; r < 4; r++) a[r] = Xs[ty * 4 + r][k];
            float4 bv = *(float4*)&Ws[k][tx * 4];
            #pragma unroll
            for (int r = 0; r < 4; r++) {
                acc[r][0] += a[r] * bv.x;
                acc[r][1] += a[r] * bv.y;
                acc[r][2] += a[r] * bv.z;
                acc[r][3] += a[r] * bv.w;
            }
        }
        __syncthreads();
    }

    #pragma unroll
    for (int r = 0; r < 4; r++) {
        int grow = row0 + ty * 4 + r;
        if (grow < n) {
            float dv = g_dinv[grow];
            float4 o = make_float4(acc[r][0] * dv, acc[r][1] * dv,
                                   acc[r][2] * dv, acc[r][3] * dv);
            *(float4*)(g_h + (size_t)grow * 64 + tx * 4) = o;
        }
    }
}

// ---------------- aggregation: warp per node ----------------
// out[v][:] = dinv[v] * (g_h[v][:] + sum_{s in row(v)} g_h[s][:]) + bias
// TO_GA: write to g_a with relu; else write to `out` (final layer, no relu).
template<bool TO_GA>
__global__ void k_agg(const float* __restrict__ bias, float* __restrict__ out, int n) {
    int warp = (blockIdx.x * blockDim.x + threadIdx.x) >> 5;
    int lane = threadIdx.x & 31;
    if (warp >= n) return;
    int v = warp;

    const float* h = (const float*)g_h;
    float2 acc = *(const float2*)(h + (size_t)v * 64 + lane * 2);
    int r0 = g_rowptr[v], r1 = g_rowptr[v + 1];
    for (int e = r0; e < r1; e++) {
        int s = __ldg(&g_col[e]);
        float2 m = *(const float2*)(h + (size_t)s * 64 + lane * 2);
        acc.x += m.x; acc.y += m.y;
    }
    float dv = g_dinv[v];
    float2 bb = *(const float2*)(bias + lane * 2);
    float ox = fmaf(dv, acc.x, bb.x);
    float oy = fmaf(dv, acc.y, bb.y);
    if (TO_GA) {
        ox = fmaxf(ox, 0.f); oy = fmaxf(oy, 0.f);
        *(float2*)(g_a + (size_t)v * 64 + lane * 2) = make_float2(ox, oy);
    } else {
        *(float2*)(out + (size_t)v * 64 + lane * 2) = make_float2(ox, oy);
    }
}

// ---------------- launch ----------------
extern "C" void kernel_launch(void* const* d_in, const int* in_sizes, int n_in,
                              void* d_out, int out_size) {
    const float* x  = (const float*)d_in[0];
    const void*  ei = d_in[1];
    const float* W1 = (const float*)d_in[2];
    const float* b1 = (const float*)d_in[3];
    const float* W2 = (const float*)d_in[4];
    const float* b2 = (const float*)d_in[5];
    float* out = (float*)d_out;

    int n = in_sizes[0] / DIN;     // 100000
    int e = in_sizes[1] / 2;       // 1000000

    k_detect<<<1, 1>>>(ei, n, e);
    k_init  <<<(n + 255) / 256, 256>>>(n);
    k_count <<<(e + 255) / 256, 256>>>(ei, n, e);
    k_scan  <<<1, 1024>>>(n);
    k_fill  <<<(e + 255) / 256, 256>>>(ei, n, e);

    // layer 1: h = dinv * (x @ W1); a = relu(dinv*(h[v]+sum h[src]) + b1)
    k_gemm<DIN, false><<<(n + 63) / 64, 256>>>(x, W1, n);
    k_agg<true><<<(n * 32 + 255) / 256, 256>>>(b1, nullptr, n);

    // layer 2: h = dinv * (a @ W2); out = dinv*(h[v]+sum h[src]) + b2
    k_gemm<DH, true><<<(n + 63) / 64, 256>>>(nullptr, W2, n);
    k_agg<false><<<(n * 32 + 255) / 256, 256>>>(b2, out, n);
}

// round 4
// speedup vs baseline: 1.9241x; 1.9241x over previous
#include <cuda_runtime.h>
#include <cstdint>

#define MAXN 100000
#define MAXE 1000000
#define DIN 128
#define DH  64
#define SCAN_CHUNK 512
#define MAXB 256   // >= ceil(MAXN/SCAN_CHUNK) = 196

// ---- scratch (no allocations allowed; referenced only from device code) ----
__device__ int   g_deg[MAXN];
__device__ int   g_rowptr[MAXN + 1];
__device__ int   g_cursor[MAXN];
__device__ int   g_col[MAXE];
__device__ float g_dinv[MAXN];
__device__ int   g_bsum[MAXB];
__device__ int   g_boff[MAXB];
__device__ __align__(16) float g_h[(size_t)MAXN * 64];  // dinv-scaled GEMM output
__device__ __align__(16) float g_a[(size_t)MAXN * 64];  // layer-1 activations
__device__ int   g_is64;                                 // edge dtype flag

// ---------------- dtype detection: int64 vs int32 edge_index ----------------
// One warp, 2 probes per lane, ballot-reduced.
__global__ void k_detect(const void* ei, int n, int e) {
    const long long* p = (const long long*)ei;
    int lane = threadIdx.x;
    int bad = 0;
    #pragma unroll
    for (int j = 0; j < 2; j++) {
        int i = lane * 2 + j;
        if (i < e) {
            long long v = p[i];
            if (v < 0 || v >= n) bad = 1;
        }
    }
    unsigned m = __ballot_sync(0xffffffffu, bad);
    if (lane == 0) g_is64 = (m == 0u);
}

// ---------------- init: zero deg + cursor ----------------
__global__ void k_init(int n) {
    int i = blockIdx.x * blockDim.x + threadIdx.x;
    if (i < n) { g_deg[i] = 0; g_cursor[i] = 0; }
}

// ---------------- degree count over dst ----------------
__global__ void k_count(const void* __restrict__ ei, int n, int e) {
    int i = blockIdx.x * blockDim.x + threadIdx.x;
    if (i >= e) return;
    int v;
    if (g_is64) v = (int)((const long long*)ei + e)[i];
    else        v = ((const int*)ei + e)[i];
    if ((unsigned)v < (unsigned)n) atomicAdd(&g_deg[v], 1);
}

// ---------------- phase A: per-block sums of deg ----------------
// 256 threads/block, 2 elements per thread (SCAN_CHUNK=512 per block).
__global__ void k_part(int n) {
    __shared__ int wsum[8];
    int b = blockIdx.x, t = threadIdx.x;
    int i0 = b * SCAN_CHUNK + t * 2;
    int d0 = (i0     < n) ? g_deg[i0]     : 0;
    int d1 = (i0 + 1 < n) ? g_deg[i0 + 1] : 0;
    int s = d0 + d1;
    #pragma unroll
    for (int off = 16; off > 0; off >>= 1)
        s += __shfl_down_sync(0xffffffffu, s, off);
    int lane = t & 31, w = t >> 5;
    if (lane == 0) wsum[w] = s;
    __syncthreads();
    if (t == 0) {
        int tot = 0;
        #pragma unroll
        for (int k = 0; k < 8; k++) tot += wsum[k];
        g_bsum[b] = tot;
    }
}

// ---------------- phase B: scan the block sums (single block) ----------------
__global__ void k_scanbsum(int nb, int n) {
    __shared__ int wtot[8];
    int t = threadIdx.x;               // 256 threads, nb <= 256
    int v = (t < nb) ? g_bsum[t] : 0;
    int lane = t & 31, w = t >> 5;
    int incl = v;
    #pragma unroll
    for (int off = 1; off < 32; off <<= 1) {
        int u = __shfl_up_sync(0xffffffffu, incl, off);
        if (lane >= off) incl += u;
    }
    if (lane == 31) wtot[w] = incl;
    __syncthreads();
    if (w == 0 && lane < 8) {
        int x = wtot[lane];
        int ix = x;
        #pragma unroll
        for (int off = 1; off < 8; off <<= 1) {
            int u = __shfl_up_sync(0xffu, ix, off);
            if (lane >= off) ix += u;
        }
        wtot[lane] = ix - x;           // exclusive warp offsets
    }
    __syncthreads();
    int excl = wtot[w] + (incl - v);
    if (t < nb) g_boff[t] = excl;
    if (t == 255) g_rowptr[n] = wtot[7] + incl - ((255 < nb) ? 0 : 0) + 0; // placeholder
    // total = exclusive prefix of imaginary element 256 = wtot[7]+incl for t=255
    if (t == 255) g_rowptr[n] = excl + v;
}

// ---------------- phase C: per-block exclusive scan -> rowptr + dinv ----------------
__global__ void k_rowptr(int n) {
    __shared__ int woff[8];
    int b = blockIdx.x, t = threadIdx.x;
    int i0 = b * SCAN_CHUNK + t * 2;
    int d0 = (i0     < n) ? g_deg[i0]     : 0;
    int d1 = (i0 + 1 < n) ? g_deg[i0 + 1] : 0;
    int s = d0 + d1;
    int lane = t & 31, w = t >> 5;
    int incl = s;
    #pragma unroll
    for (int off = 1; off < 32; off <<= 1) {
        int u = __shfl_up_sync(0xffffffffu, incl, off);
        if (lane >= off) incl += u;
    }
    if (lane == 31) woff[w] = incl;
    __syncthreads();
    if (w == 0 && lane < 8) {
        int x = woff[lane];
        int ix = x;
        #pragma unroll
        for (int off = 1; off < 8; off <<= 1) {
            int u = __shfl_up_sync(0xffu, ix, off);
            if (lane >= off) ix += u;
        }
        woff[lane] = ix - x;
    }
    __syncthreads();
    int base = g_boff[b] + woff[w] + (incl - s);
    if (i0 < n) {
        g_rowptr[i0] = base;
        g_dinv[i0]   = rsqrtf((float)(d0 + 1));
    }
    if (i0 + 1 < n) {
        g_rowptr[i0 + 1] = base + d0;
        g_dinv[i0 + 1]   = rsqrtf((float)(d1 + 1));
    }
}

// ---------------- CSR fill (counting-sort placement) ----------------
__global__ void k_fill(const void* __restrict__ ei, int n, int e) {
    int i = blockIdx.x * blockDim.x + threadIdx.x;
    if (i >= e) return;
    int s, v;
    if (g_is64) {
        s = (int)((const long long*)ei)[i];
        v = (int)((const long long*)ei + e)[i];
    } else {
        s = ((const int*)ei)[i];
        v = ((const int*)ei + e)[i];
    }
    if ((unsigned)v < (unsigned)n && (unsigned)s < (unsigned)n) {
        int pos = g_rowptr[v] + atomicAdd(&g_cursor[v], 1);
        g_col[pos] = s;
    }
}

// ---------------- GEMM: g_h[i][j] = dinv[i] * dot(in[i,:], W[:,j]) ----------------
template<int K, bool FROM_GA>
__global__ void k_gemm(const float* __restrict__ in, const float* __restrict__ W, int n) {
    const int BM = 64, BK = 64;
    __shared__ float Xs[BM][BK + 4];
    __shared__ float Ws[BK][64];
    int tid = threadIdx.x;
    int tx = tid & 15, ty = tid >> 4;
    int row0 = blockIdx.x * BM;

    const float* src = FROM_GA ? (const float*)g_a : in;

    float acc[4][4] = {};

    for (int k0 = 0; k0 < K; k0 += BK) {
        for (int l = tid; l < BK * 64 / 4; l += 256) {
            ((float4*)Ws)[l] = ((const float4*)(W + (size_t)k0 * 64))[l];
        }
        for (int l = tid; l < BM * BK / 4; l += 256) {
            int r = l >> 4;
            int c4 = l & 15;
            int grow = row0 + r;
            float4 v = make_float4(0.f, 0.f, 0.f, 0.f);
            if (grow < n)
                v = *(const float4*)(src + (size_t)grow * K + k0 + c4 * 4);
            *(float4*)&Xs[r][c4 * 4] = v;
        }
        __syncthreads();

        #pragma unroll
        for (int k = 0; k < BK; k++) {
            float a[4];
            #pragma unroll
            for (int r = 0; r < 4; r++) a[r] = Xs[ty * 4 + r][k];
            float4 bv = *(float4*)&Ws[k][tx * 4];
            #pragma unroll
            for (int r = 0; r < 4; r++) {
                acc[r][0] += a[r] * bv.x;
                acc[r][1] += a[r] * bv.y;
                acc[r][2] += a[r] * bv.z;
                acc[r][3] += a[r] * bv.w;
            }
        }
        __syncthreads();
    }

    #pragma unroll
    for (int r = 0; r < 4; r++) {
        int grow = row0 + ty * 4 + r;
        if (grow < n) {
            float dv = g_dinv[grow];
            float4 o = make_float4(acc[r][0] * dv, acc[r][1] * dv,
                                   acc[r][2] * dv, acc[r][3] * dv);
            *(float4*)(g_h + (size_t)grow * 64 + tx * 4) = o;
        }
    }
}

// ---------------- aggregation: warp per node ----------------
template<bool TO_GA>
__global__ void k_agg(const float* __restrict__ bias, float* __restrict__ out, int n) {
    int warp = (blockIdx.x * blockDim.x + threadIdx.x) >> 5;
    int lane = threadIdx.x & 31;
    if (warp >= n) return;
    int v = warp;

    const float* h = (const float*)g_h;
    float2 acc = *(const float2*)(h + (size_t)v * 64 + lane * 2);
    int r0 = g_rowptr[v], r1 = g_rowptr[v + 1];
    int e = r0;
    // unroll by 2 for MLP on the col->h dependent chain
    for (; e + 1 < r1; e += 2) {
        int s0 = __ldg(&g_col[e]);
        int s1 = __ldg(&g_col[e + 1]);
        float2 m0 = *(const float2*)(h + (size_t)s0 * 64 + lane * 2);
        float2 m1 = *(const float2*)(h + (size_t)s1 * 64 + lane * 2);
        acc.x += m0.x + m1.x; acc.y += m0.y + m1.y;
    }
    if (e < r1) {
        int s0 = __ldg(&g_col[e]);
        float2 m0 = *(const float2*)(h + (size_t)s0 * 64 + lane * 2);
        acc.x += m0.x; acc.y += m0.y;
    }
    float dv = g_dinv[v];
    float2 bb = *(const float2*)(bias + lane * 2);
    float ox = fmaf(dv, acc.x, bb.x);
    float oy = fmaf(dv, acc.y, bb.y);
    if (TO_GA) {
        ox = fmaxf(ox, 0.f); oy = fmaxf(oy, 0.f);
        *(float2*)(g_a + (size_t)v * 64 + lane * 2) = make_float2(ox, oy);
    } else {
        *(float2*)(out + (size_t)v * 64 + lane * 2) = make_float2(ox, oy);
    }
}

// ---------------- launch ----------------
extern "C" void kernel_launch(void* const* d_in, const int* in_sizes, int n_in,
                              void* d_out, int out_size) {
    const float* x  = (const float*)d_in[0];
    const void*  ei = d_in[1];
    const float* W1 = (const float*)d_in[2];
    const float* b1 = (const float*)d_in[3];
    const float* W2 = (const float*)d_in[4];
    const float* b2 = (const float*)d_in[5];
    float* out = (float*)d_out;

    int n = in_sizes[0] / DIN;     // 100000
    int e = in_sizes[1] / 2;       // 1000000
    int nb = (n + SCAN_CHUNK - 1) / SCAN_CHUNK;   // 196

    k_detect  <<<1, 32>>>(ei, n, e);
    k_init    <<<(n + 255) / 256, 256>>>(n);
    k_count   <<<(e + 255) / 256, 256>>>(ei, n, e);
    k_part    <<<nb, 256>>>(n);
    k_scanbsum<<<1, 256>>>(nb, n);
    k_rowptr  <<<nb, 256>>>(n);
    k_fill    <<<(e + 255) / 256, 256>>>(ei, n, e);

    // layer 1: h = dinv * (x @ W1); a = relu(dinv*(h[v]+sum h[src]) + b1)
    k_gemm<DIN, false><<<(n + 63) / 64, 256>>>(x, W1, n);
    k_agg<true><<<(n * 32 + 255) / 256, 256>>>(b1, nullptr, n);

    // layer 2: h = dinv * (a @ W2); out = dinv*(h[v]+sum h[src]) + b2
    k_gemm<DH, true><<<(n + 63) / 64, 256>>>(nullptr, W2, n);
    k_agg<false><<<(n * 32 + 255) / 256, 256>>>(b2, out, n);
}